// round 2
// baseline (speedup 1.0000x reference)
#include <cuda_runtime.h>
#include <cstdint>
#include <math_constants.h>

// ---------------------------------------------------------------------------
// TorchLMHeadGRPO fused kernel, Round 1: exact-fp32 SIMT GEMM + fused row stats
//
// Pipeline (5 launches, graph-capturable, no allocations):
//   1) gemm_stats<0>  : logits = x @ W^T, per (row, col-tile) partial
//                       {max, argmax, sum, sumexp} -> g_part
//   2) reduce_rows_x  : merge partials per row -> chosen token, chosen_lp,
//                       lse, sum(logits)
//   3) gemm_stats<1>  : ref_logits = ref @ refW^T, partial {max,sumexp} +
//                       extract ref_logit[chosen]
//   4) reduce_rows_ref: merge -> ref_lse -> kl per row
//   5) finalize       : masked reductions -> out[4] = {loss, m1, m2, m3}
// ---------------------------------------------------------------------------

#define TM 128
#define TN 128
#define TK 8
#define NTHREADS 256

#define MAX_M  4096
#define MAX_CT 256

// ------------------------- static device scratch ---------------------------
__device__ float4 g_part[(size_t)MAX_M * MAX_CT];   // 16 MB partial stats
__device__ int    g_chosen[MAX_M];
__device__ float  g_chosen_lp[MAX_M];
__device__ float  g_lse[MAX_M];
__device__ float  g_sumlogits[MAX_M];
__device__ float  g_refchosen[MAX_M];
__device__ float  g_kl[MAX_M];

// ------------------------- packed f32x2 helpers ----------------------------
__device__ __forceinline__ unsigned long long pack2_dup(float a) {
#if defined(__CUDA_ARCH__) && (__CUDA_ARCH__ >= 1000)
    unsigned long long r;
    asm("mov.b64 %0, {%1, %1};" : "=l"(r) : "r"(__float_as_uint(a)));
    return r;
#else
    unsigned long long lo = __float_as_uint(a);
    return lo | (lo << 32);
#endif
}

__device__ __forceinline__ void fma2(unsigned long long& c,
                                     unsigned long long a,
                                     unsigned long long b) {
#if defined(__CUDA_ARCH__) && (__CUDA_ARCH__ >= 1000)
    asm("fma.rn.f32x2 %0, %1, %2, %0;" : "+l"(c) : "l"(a), "l"(b));
#else
    float clo = __uint_as_float((unsigned)c), chi = __uint_as_float((unsigned)(c >> 32));
    float alo = __uint_as_float((unsigned)a), ahi = __uint_as_float((unsigned)(a >> 32));
    float blo = __uint_as_float((unsigned)b), bhi = __uint_as_float((unsigned)(b >> 32));
    clo = fmaf(alo, blo, clo);
    chi = fmaf(ahi, bhi, chi);
    c = (unsigned long long)__float_as_uint(clo) |
        ((unsigned long long)__float_as_uint(chi) << 32);
#endif
}

__device__ __forceinline__ float lo32(unsigned long long v) {
    return __uint_as_float((unsigned)v);
}
__device__ __forceinline__ float hi32(unsigned long long v) {
    return __uint_as_float((unsigned)(v >> 32));
}

// ---------------------------------------------------------------------------
// Fused GEMM + per-(row, col-tile) stats.
// C[m, v] = dot(X[m, :], Wm[v, :]),  X: [M, H] row-major, Wm: [V, H] row-major.
// MODE 0: write {max, sum, sumexp, argmax} partials.
// MODE 1: same partials (sum/argmax unused downstream) + extract value at
//         column g_chosen[row] into g_refchosen[row].
// ---------------------------------------------------------------------------
template <int MODE>
__global__ __launch_bounds__(NTHREADS, 2)
void gemm_stats_kernel(const float* __restrict__ X,
                       const float* __restrict__ Wm,
                       int M, int V, int H, int nct)
{
    __shared__ float As[TK][TM];
    __shared__ float Bs[TK][TN];

    const int m0 = blockIdx.x * TM;   // row tile (fast-varying for W L2 reuse)
    const int c0 = blockIdx.y * TN;   // col tile

    const int tid   = threadIdx.x;
    const int tx    = tid & 15;
    const int ty    = tid >> 4;
    const int lrow  = tid >> 1;       // 0..127  (loader row within tile)
    const int lquad = tid & 1;        // which float4 of the 8-wide K slice

    // clamped global rows for the loaders (exact-divisible dims in practice)
    int xr = m0 + lrow; if (xr > M - 1) xr = M - 1;
    int wr = c0 + lrow; if (wr > V - 1) wr = V - 1;
    const float* xptr = X  + (size_t)xr * H + lquad * 4;
    const float* wptr = Wm + (size_t)wr * H + lquad * 4;

    unsigned long long acc[8][4];
#pragma unroll
    for (int i = 0; i < 8; i++)
#pragma unroll
        for (int j = 0; j < 4; j++) acc[i][j] = 0ull;

    for (int k0 = 0; k0 < H; k0 += TK) {
        float4 av = *(const float4*)(xptr + k0);
        float4 bv = *(const float4*)(wptr + k0);
        __syncthreads();   // previous iteration's reads done
        As[lquad * 4 + 0][lrow] = av.x;
        As[lquad * 4 + 1][lrow] = av.y;
        As[lquad * 4 + 2][lrow] = av.z;
        As[lquad * 4 + 3][lrow] = av.w;
        Bs[lquad * 4 + 0][lrow] = bv.x;
        Bs[lquad * 4 + 1][lrow] = bv.y;
        Bs[lquad * 4 + 2][lrow] = bv.z;
        Bs[lquad * 4 + 3][lrow] = bv.w;
        __syncthreads();

#pragma unroll
        for (int k = 0; k < TK; k++) {
            float4 a0 = *(const float4*)&As[k][ty * 4];
            float4 a1 = *(const float4*)&As[k][64 + ty * 4];
            ulonglong2 b0 = *(const ulonglong2*)&Bs[k][tx * 4];
            ulonglong2 b1 = *(const ulonglong2*)&Bs[k][64 + tx * 4];
            unsigned long long bp[4] = { b0.x, b0.y, b1.x, b1.y };
            float a[8] = { a0.x, a0.y, a0.z, a0.w, a1.x, a1.y, a1.z, a1.w };
#pragma unroll
            for (int i = 0; i < 8; i++) {
                unsigned long long a2 = pack2_dup(a[i]);
#pragma unroll
                for (int j = 0; j < 4; j++) fma2(acc[i][j], a2, bp[j]);
            }
        }
    }

    // ---------------- epilogue: per-row partial stats ----------------
    // thread owns rows {ty*4+i, 64+ty*4+i}, cols {tx*4+j, 64+tx*4+j}
    const int cbase = c0 + tx * 4;

#pragma unroll
    for (int i = 0; i < 8; i++) {
        const int rr   = (i < 4) ? (ty * 4 + i) : (64 + ty * 4 + (i - 4));
        const int grow = m0 + rr;

        float v[8];
        v[0] = lo32(acc[i][0]); v[1] = hi32(acc[i][0]);
        v[2] = lo32(acc[i][1]); v[3] = hi32(acc[i][1]);
        v[4] = lo32(acc[i][2]); v[5] = hi32(acc[i][2]);
        v[6] = lo32(acc[i][3]); v[7] = hi32(acc[i][3]);
        int cc[8];
        cc[0] = cbase + 0;  cc[1] = cbase + 1;
        cc[2] = cbase + 2;  cc[3] = cbase + 3;
        cc[4] = cbase + 64; cc[5] = cbase + 65;
        cc[6] = cbase + 66; cc[7] = cbase + 67;

        // local scan (ascending col order -> first-occurrence tie-break)
        float lmax = v[0]; int larg = cc[0]; float lsum = v[0];
#pragma unroll
        for (int j = 1; j < 8; j++) {
            lsum += v[j];
            if (v[j] > lmax) { lmax = v[j]; larg = cc[j]; }
        }

        // reduce across the 16 lanes sharing this row (lanes (ty&1)*16 + tx)
#pragma unroll
        for (int o = 8; o >= 1; o >>= 1) {
            float om = __shfl_xor_sync(0xffffffffu, lmax, o);
            int   oa = __shfl_xor_sync(0xffffffffu, larg, o);
            float os = __shfl_xor_sync(0xffffffffu, lsum, o);
            lsum += os;
            if (om > lmax || (om == lmax && oa < larg)) { lmax = om; larg = oa; }
        }

        float lexp = 0.f;
#pragma unroll
        for (int j = 0; j < 8; j++) lexp += expf(v[j] - lmax);
#pragma unroll
        for (int o = 8; o >= 1; o >>= 1)
            lexp += __shfl_xor_sync(0xffffffffu, lexp, o);

        if (MODE == 1 && grow < M) {
            int ch = g_chosen[grow];
#pragma unroll
            for (int j = 0; j < 8; j++)
                if (cc[j] == ch) g_refchosen[grow] = v[j];
        }

        if (tx == 0 && grow < M) {
            float4 p;
            p.x = lmax; p.y = lsum; p.z = lexp; p.w = __int_as_float(larg);
            g_part[(size_t)grow * nct + blockIdx.y] = p;
        }
    }
}

// ---------------------------------------------------------------------------
// Per-row merge of col-tile partials. One warp per row.
// ---------------------------------------------------------------------------
__global__ void reduce_rows_x(int M, int nct)
{
    const int gw   = (blockIdx.x * blockDim.x + threadIdx.x) >> 5;
    const int lane = threadIdx.x & 31;
    if (gw >= M) return;

    float mx = -CUDART_INF_F, se = 0.f, sum = 0.f;
    int   arg = 0x7fffffff;
    const float4* base = g_part + (size_t)gw * nct;

    for (int j = lane; j < nct; j += 32) {
        float4 p = base[j];
        float pm = p.x;
        float nm = fmaxf(mx, pm);
        float e1 = (se  > 0.f) ? expf(mx - nm) : 0.f;
        float e2 = (p.z > 0.f) ? expf(pm - nm) : 0.f;
        se = se * e1 + p.z * e2;
        int pa = __float_as_int(p.w);
        if (pm > mx || (pm == mx && pa < arg)) arg = pa;
        mx = nm;
        sum += p.y;
    }
#pragma unroll
    for (int o = 16; o >= 1; o >>= 1) {
        float om   = __shfl_xor_sync(0xffffffffu, mx,  o);
        float ose  = __shfl_xor_sync(0xffffffffu, se,  o);
        float osum = __shfl_xor_sync(0xffffffffu, sum, o);
        int   oa   = __shfl_xor_sync(0xffffffffu, arg, o);
        float nm = fmaxf(mx, om);
        float e1 = (se  > 0.f) ? expf(mx - nm) : 0.f;
        float e2 = (ose > 0.f) ? expf(om - nm) : 0.f;
        se = se * e1 + ose * e2;
        if (om > mx || (om == mx && oa < arg)) arg = oa;
        mx = nm;
        sum += osum;
    }
    if (lane == 0) {
        float lse = mx + logf(se);
        g_chosen[gw]    = arg;
        g_lse[gw]       = lse;
        g_sumlogits[gw] = sum;
        g_chosen_lp[gw] = mx - lse;   // max logit minus lse
    }
}

__global__ void reduce_rows_ref(int M, int nct)
{
    const int gw   = (blockIdx.x * blockDim.x + threadIdx.x) >> 5;
    const int lane = threadIdx.x & 31;
    if (gw >= M) return;

    float mx = -CUDART_INF_F, se = 0.f;
    const float4* base = g_part + (size_t)gw * nct;

    for (int j = lane; j < nct; j += 32) {
        float4 p = base[j];
        float pm = p.x;
        float nm = fmaxf(mx, pm);
        float e1 = (se  > 0.f) ? expf(mx - nm) : 0.f;
        float e2 = (p.z > 0.f) ? expf(pm - nm) : 0.f;
        se = se * e1 + p.z * e2;
        mx = nm;
    }
#pragma unroll
    for (int o = 16; o >= 1; o >>= 1) {
        float om  = __shfl_xor_sync(0xffffffffu, mx, o);
        float ose = __shfl_xor_sync(0xffffffffu, se, o);
        float nm = fmaxf(mx, om);
        float e1 = (se  > 0.f) ? expf(mx - nm) : 0.f;
        float e2 = (ose > 0.f) ? expf(om - nm) : 0.f;
        se = se * e1 + ose * e2;
        mx = nm;
    }
    if (lane == 0) {
        float rlse   = mx + logf(se);
        float ref_lp = g_refchosen[gw] - rlse;
        float delta  = ref_lp - g_chosen_lp[gw];
        g_kl[gw] = expf(delta) - delta - 1.0f;
    }
}

// ---------------------------------------------------------------------------
// Final masked reductions -> out[4] = {loss, m1, m2, m3}
// ---------------------------------------------------------------------------
__global__ void finalize_kernel(const float* __restrict__ attn,
                                const float* __restrict__ adv,
                                int Bn, int T, int M, int V,
                                float* __restrict__ out)
{
    __shared__ double s_loss, s_mask, s_m1, s_m2;
    __shared__ double s_klb[64], s_mb[64];
    const int tid = threadIdx.x;
    if (tid == 0) { s_loss = 0.0; s_mask = 0.0; s_m1 = 0.0; s_m2 = 0.0; }
    if (tid < 64) { s_klb[tid] = 0.0; s_mb[tid] = 0.0; }
    __syncthreads();

    double l = 0.0, mk = 0.0, a1 = 0.0, a2 = 0.0;
    for (int r = tid; r < M; r += blockDim.x) {
        int b = r / T;
        float m  = attn[r];
        float kl = g_kl[r];
        float lp = g_chosen_lp[r];
        // literal GRPO terms (coef_1 == exp(0) == 1, coef_2 == clip(1,.8,1.2) == 1)
        float c1 = expf(lp - lp);
        float c2 = fminf(fmaxf(c1, 1.0f - 0.2f), 1.0f + 0.2f);
        float a  = adv[b];
        float ptl = -fminf(c1 * a, c2 * a) + 0.1f * kl;

        l  += (double)(ptl * m);
        mk += (double)m;
        a1 += (double)lp;
        a2 += (double)g_sumlogits[r] / (double)V - (double)g_lse[r];
        atomicAdd(&s_klb[b], (double)(kl * m));
        atomicAdd(&s_mb[b],  (double)m);
    }
    atomicAdd(&s_loss, l);
    atomicAdd(&s_mask, mk);
    atomicAdd(&s_m1,   a1);
    atomicAdd(&s_m2,   a2);
    __syncthreads();

    if (tid == 0) {
        double m3 = 0.0;
        for (int b = 0; b < Bn; b++) m3 += s_klb[b] / fmax(s_mb[b], 1.0);
        m3 /= (double)Bn;
        out[0] = (float)(s_loss / fmax(s_mask, 1.0));
        out[1] = (float)(s_m1 / (double)M);
        out[2] = (float)(s_m2 / (double)M);
        out[3] = (float)m3;
    }
}

// ---------------------------------------------------------------------------
extern "C" void kernel_launch(void* const* d_in, const int* in_sizes, int n_in,
                              void* d_out, int out_size)
{
    const float* x    = (const float*)d_in[0];
    const float* attn = (const float*)d_in[1];
    const float* adv  = (const float*)d_in[2];
    const float* ref  = (const float*)d_in[3];
    const float* Wm   = (const float*)d_in[4];
    const float* refW = (const float*)d_in[5];

    const int BT = in_sizes[1];          // B*T (attention_mask elements)
    const int Bn = in_sizes[2];          // B   (advantages elements)
    const int T  = BT / Bn;
    const int H  = in_sizes[0] / BT;     // hidden
    const int V  = in_sizes[4] / H;      // vocab
    const int M  = BT;

    const int nct = (V + TN - 1) / TN;   // col tiles (250 for V=32000)
    if (M > MAX_M || nct > MAX_CT) return;  // unsupported shape (never hit)

    dim3 grid((M + TM - 1) / TM, nct);   // x = row tile (fast) -> W tile L2 reuse

    gemm_stats_kernel<0><<<grid, NTHREADS>>>(x, Wm, M, V, H, nct);
    reduce_rows_x<<<(M * 32 + 255) / 256, 256>>>(M, nct);
    gemm_stats_kernel<1><<<grid, NTHREADS>>>(ref, refW, M, V, H, nct);
    reduce_rows_ref<<<(M * 32 + 255) / 256, 256>>>(M, nct);
    finalize_kernel<<<1, 1024>>>(attn, adv, Bn, T, M, V, (float*)d_out);
}

// round 3
// speedup vs baseline: 1.3868x; 1.3868x over previous
#include <cuda_runtime.h>
#include <cstdint>
#include <math_constants.h>

// ---------------------------------------------------------------------------
// TorchLMHeadGRPO, Round 2: 3xTF32 tensor-core GEMM (mma.sync.m16n8k8) with
// fused per-row {max, argmax, sum, sumexp} epilogue.
//
// Pipeline (5 launches):
//   1) gemm_stats_tc<0> : logits = x @ W^T      -> per (row, 32-col chunk) partials
//   2) reduce_rows_x    : merge -> chosen tok, chosen_lp, lse, sum(logits)
//   3) gemm_stats_tc<1> : ref_logits = ref@refW^T -> partials + ref_logit[chosen]
//   4) reduce_rows_ref  : merge -> kl per row
//   5) finalize         : masked reductions -> out[4]
// ---------------------------------------------------------------------------

#define BM 128
#define BN 128
#define BK 16
#define NSTAGE 4
#define NTHREADS 256
#define SROW 20                      // padded smem row stride (floats)
#define STAGE_FLTS (BM * SROW)       // 2560 floats per operand per stage
#define SMEM_BYTES (NSTAGE * STAGE_FLTS * 2 * 4)   // 81920 B

#define MAX_M   4096
#define MAX_CTW 1024                 // 32-col chunks (V/32 = 1000)

// ------------------------- static device scratch ---------------------------
__device__ float4 g_part[(size_t)MAX_M * MAX_CTW];  // 64 MB partial stats
__device__ int    g_chosen[MAX_M];
__device__ float  g_chosen_lp[MAX_M];
__device__ float  g_lse[MAX_M];
__device__ float  g_sumlogits[MAX_M];
__device__ float  g_refchosen[MAX_M];
__device__ float  g_kl[MAX_M];

// ------------------------- small helpers -----------------------------------
__device__ __forceinline__ float tf32_lo(float x) {
    // residual below the tf32 truncation the MMA hardware applies
    float h = __uint_as_float(__float_as_uint(x) & 0xffffe000u);
    return x - h;
}

__device__ __forceinline__ void cp_async16(uint32_t dst, const float* src) {
    asm volatile("cp.async.cg.shared.global [%0], [%1], 16;\n" :: "r"(dst), "l"(src));
}
__device__ __forceinline__ void cp_commit() {
    asm volatile("cp.async.commit_group;\n");
}
template <int N>
__device__ __forceinline__ void cp_wait() {
    asm volatile("cp.async.wait_group %0;\n" :: "n"(N));
}

__device__ __forceinline__ void mma_tf32(float* c, const float* a, const float* b) {
    asm volatile(
        "mma.sync.aligned.m16n8k8.row.col.f32.tf32.tf32.f32 "
        "{%0,%1,%2,%3}, {%4,%5,%6,%7}, {%8,%9}, {%0,%1,%2,%3};\n"
        : "+f"(c[0]), "+f"(c[1]), "+f"(c[2]), "+f"(c[3])
        : "r"(__float_as_uint(a[0])), "r"(__float_as_uint(a[1])),
          "r"(__float_as_uint(a[2])), "r"(__float_as_uint(a[3])),
          "r"(__float_as_uint(b[0])), "r"(__float_as_uint(b[1])));
}

// ---------------------------------------------------------------------------
// Tensor-core GEMM + fused stats. C[m, v] = dot(X[m,:], Wm[v,:]).
// X: [M, H] row-major, Wm: [V, H] row-major (so B tile is naturally k-major
// per column => mma "row.col" layout).
// ---------------------------------------------------------------------------
template <int MODE>
__global__ __launch_bounds__(NTHREADS)
void gemm_stats_tc(const float* __restrict__ X,
                   const float* __restrict__ Wm,
                   int M, int V, int H, int nctw)
{
    extern __shared__ float sm[];
    float* As = sm;                         // [NSTAGE][BM][SROW]
    float* Bs = sm + NSTAGE * STAGE_FLTS;   // [NSTAGE][BN][SROW]

    const int tid  = threadIdx.x;
    const int lane = tid & 31;
    const int warp = tid >> 5;
    const int wm   = warp >> 2;             // 0..1  (64-row band)
    const int wn   = warp & 3;              // 0..3  (32-col band)
    const int lg   = lane >> 2;             // 0..7
    const int lq   = lane & 3;              // 0..3

    const int m0 = blockIdx.x * BM;
    const int c0 = blockIdx.y * BN;

    // ---- loader mapping: 512 16B-chunks per operand per stage, 2/thread ----
    const int lrow = tid >> 2;              // 0..63
    const int lk4  = (tid & 3) * 4;         // k offset of this 16B chunk
    const float* aSrc0 = X  + (size_t)(m0 + lrow) * H + lk4;
    const float* aSrc1 = aSrc0 + (size_t)64 * H;
    const float* bSrc0 = Wm + (size_t)(c0 + lrow) * H + lk4;
    const float* bSrc1 = bSrc0 + (size_t)64 * H;

    const uint32_t aD0 = (uint32_t)__cvta_generic_to_shared(As + lrow * SROW + lk4);
    const uint32_t aD1 = aD0 + 64 * SROW * 4;
    const uint32_t bD0 = (uint32_t)__cvta_generic_to_shared(Bs + lrow * SROW + lk4);
    const uint32_t bD1 = bD0 + 64 * SROW * 4;

    const int KT = H / BK;                  // 128

    float acc[4][4][4];
#pragma unroll
    for (int i = 0; i < 4; i++)
#pragma unroll
        for (int j = 0; j < 4; j++)
#pragma unroll
            for (int e = 0; e < 4; e++) acc[i][j][e] = 0.f;

    // ---- prologue: fill NSTAGE-1 stages ----
#pragma unroll
    for (int s = 0; s < NSTAGE - 1; s++) {
        const int k0 = s * BK;
        const uint32_t so = s * STAGE_FLTS * 4;
        cp_async16(aD0 + so, aSrc0 + k0);
        cp_async16(aD1 + so, aSrc1 + k0);
        cp_async16(bD0 + so, bSrc0 + k0);
        cp_async16(bD1 + so, bSrc1 + k0);
        cp_commit();
    }

    for (int kt = 0; kt < KT; kt++) {
        cp_wait<NSTAGE - 2>();
        __syncthreads();

        // prefetch stage kt + NSTAGE-1
        const int kn = kt + NSTAGE - 1;
        if (kn < KT) {
            const int s = kn & (NSTAGE - 1);
            const int k0 = kn * BK;
            const uint32_t so = s * STAGE_FLTS * 4;
            cp_async16(aD0 + so, aSrc0 + k0);
            cp_async16(aD1 + so, aSrc1 + k0);
            cp_async16(bD0 + so, bSrc0 + k0);
            cp_async16(bD1 + so, bSrc1 + k0);
            cp_commit();
        }

        const float* A = As + (kt & (NSTAGE - 1)) * STAGE_FLTS;
        const float* B = Bs + (kt & (NSTAGE - 1)) * STAGE_FLTS;

#pragma unroll
        for (int kb = 0; kb < BK; kb += 8) {
            float ar[4][4], al[4][4];
#pragma unroll
            for (int i = 0; i < 4; i++) {
                const int r0 = (wm * 64 + i * 16 + lg) * SROW + kb + lq;
                ar[i][0] = A[r0];
                ar[i][1] = A[r0 + 8 * SROW];
                ar[i][2] = A[r0 + 4];
                ar[i][3] = A[r0 + 8 * SROW + 4];
#pragma unroll
                for (int e = 0; e < 4; e++) al[i][e] = tf32_lo(ar[i][e]);
            }
            float br[4][2], bl[4][2];
#pragma unroll
            for (int j = 0; j < 4; j++) {
                const int n0 = (wn * 32 + j * 8 + lg) * SROW + kb + lq;
                br[j][0] = B[n0];
                br[j][1] = B[n0 + 4];
                bl[j][0] = tf32_lo(br[j][0]);
                bl[j][1] = tf32_lo(br[j][1]);
            }
#pragma unroll
            for (int i = 0; i < 4; i++)
#pragma unroll
                for (int j = 0; j < 4; j++) {
                    mma_tf32(acc[i][j], ar[i], br[j]);   // hi*hi (HW truncates)
                    mma_tf32(acc[i][j], al[i], br[j]);   // lo*hi
                    mma_tf32(acc[i][j], ar[i], bl[j]);   // hi*lo
                }
        }
    }

    // ---------------- epilogue: per-row partial stats ----------------
    // thread owns rows: m0 + wm*64 + i*16 + g*8 + lg   (i=0..3, g=0..1)
    //          cols:    c0 + wn*32 + j*8 + 2*lq + e    (j=0..3, e=0..1)
    const int chunk = blockIdx.y * 4 + wn;
    const int cbase = c0 + wn * 32 + 2 * lq;

#pragma unroll
    for (int i = 0; i < 4; i++) {
#pragma unroll
        for (int g = 0; g < 2; g++) {
            const int grow = m0 + wm * 64 + i * 16 + g * 8 + lg;
            float v[8];
            int   cc[8];
#pragma unroll
            for (int j = 0; j < 4; j++) {
                v[2 * j]     = acc[i][j][2 * g];
                v[2 * j + 1] = acc[i][j][2 * g + 1];
                cc[2 * j]     = cbase + j * 8;
                cc[2 * j + 1] = cbase + j * 8 + 1;
            }
            // local scan (ascending col order)
            float lmax = v[0]; int larg = cc[0]; float lsum = v[0];
#pragma unroll
            for (int t = 1; t < 8; t++) {
                lsum += v[t];
                if (v[t] > lmax) { lmax = v[t]; larg = cc[t]; }
            }
            // merge across the 4 lanes sharing this row (xor 1, 2)
#pragma unroll
            for (int o = 2; o >= 1; o >>= 1) {
                float om = __shfl_xor_sync(0xffffffffu, lmax, o);
                int   oa = __shfl_xor_sync(0xffffffffu, larg, o);
                float os = __shfl_xor_sync(0xffffffffu, lsum, o);
                lsum += os;
                if (om > lmax || (om == lmax && oa < larg)) { lmax = om; larg = oa; }
            }
            float lexp = 0.f;
#pragma unroll
            for (int t = 0; t < 8; t++) lexp += __expf(v[t] - lmax);
#pragma unroll
            for (int o = 2; o >= 1; o >>= 1)
                lexp += __shfl_xor_sync(0xffffffffu, lexp, o);

            if (MODE == 1) {
                const int ch = g_chosen[grow];
#pragma unroll
                for (int t = 0; t < 8; t++)
                    if (cc[t] == ch) g_refchosen[grow] = v[t];
            }
            if (lq == 0) {
                float4 p;
                p.x = lmax; p.y = lsum; p.z = lexp; p.w = __int_as_float(larg);
                g_part[(size_t)grow * nctw + chunk] = p;
            }
        }
    }
}

// ---------------------------------------------------------------------------
// Per-row merge of col-chunk partials. One warp per row.
// ---------------------------------------------------------------------------
__global__ void reduce_rows_x(int M, int nct)
{
    const int gw   = (blockIdx.x * blockDim.x + threadIdx.x) >> 5;
    const int lane = threadIdx.x & 31;
    if (gw >= M) return;

    float mx = -CUDART_INF_F, se = 0.f, sum = 0.f;
    int   arg = 0x7fffffff;
    const float4* base = g_part + (size_t)gw * nct;

    for (int j = lane; j < nct; j += 32) {
        float4 p = base[j];
        float pm = p.x;
        float nm = fmaxf(mx, pm);
        float e1 = (se  > 0.f) ? expf(mx - nm) : 0.f;
        float e2 = (p.z > 0.f) ? expf(pm - nm) : 0.f;
        se = se * e1 + p.z * e2;
        int pa = __float_as_int(p.w);
        if (pm > mx || (pm == mx && pa < arg)) arg = pa;
        mx = nm;
        sum += p.y;
    }
#pragma unroll
    for (int o = 16; o >= 1; o >>= 1) {
        float om   = __shfl_xor_sync(0xffffffffu, mx,  o);
        float ose  = __shfl_xor_sync(0xffffffffu, se,  o);
        float osum = __shfl_xor_sync(0xffffffffu, sum, o);
        int   oa   = __shfl_xor_sync(0xffffffffu, arg, o);
        float nm = fmaxf(mx, om);
        float e1 = (se  > 0.f) ? expf(mx - nm) : 0.f;
        float e2 = (ose > 0.f) ? expf(om - nm) : 0.f;
        se = se * e1 + ose * e2;
        if (om > mx || (om == mx && oa < arg)) arg = oa;
        mx = nm;
        sum += osum;
    }
    if (lane == 0) {
        float lse = mx + logf(se);
        g_chosen[gw]    = arg;
        g_lse[gw]       = lse;
        g_sumlogits[gw] = sum;
        g_chosen_lp[gw] = mx - lse;
    }
}

__global__ void reduce_rows_ref(int M, int nct)
{
    const int gw   = (blockIdx.x * blockDim.x + threadIdx.x) >> 5;
    const int lane = threadIdx.x & 31;
    if (gw >= M) return;

    float mx = -CUDART_INF_F, se = 0.f;
    const float4* base = g_part + (size_t)gw * nct;

    for (int j = lane; j < nct; j += 32) {
        float4 p = base[j];
        float pm = p.x;
        float nm = fmaxf(mx, pm);
        float e1 = (se  > 0.f) ? expf(mx - nm) : 0.f;
        float e2 = (p.z > 0.f) ? expf(pm - nm) : 0.f;
        se = se * e1 + p.z * e2;
        mx = nm;
    }
#pragma unroll
    for (int o = 16; o >= 1; o >>= 1) {
        float om  = __shfl_xor_sync(0xffffffffu, mx, o);
        float ose = __shfl_xor_sync(0xffffffffu, se, o);
        float nm = fmaxf(mx, om);
        float e1 = (se  > 0.f) ? expf(mx - nm) : 0.f;
        float e2 = (ose > 0.f) ? expf(om - nm) : 0.f;
        se = se * e1 + ose * e2;
        mx = nm;
    }
    if (lane == 0) {
        float rlse   = mx + logf(se);
        float ref_lp = g_refchosen[gw] - rlse;
        float delta  = ref_lp - g_chosen_lp[gw];
        g_kl[gw] = expf(delta) - delta - 1.0f;
    }
}

// ---------------------------------------------------------------------------
// Final masked reductions -> out[4] = {loss, m1, m2, m3}
// ---------------------------------------------------------------------------
__global__ void finalize_kernel(const float* __restrict__ attn,
                                const float* __restrict__ adv,
                                int Bn, int T, int M, int V,
                                float* __restrict__ out)
{
    __shared__ double s_loss, s_mask, s_m1, s_m2;
    __shared__ double s_klb[64], s_mb[64];
    const int tid = threadIdx.x;
    if (tid == 0) { s_loss = 0.0; s_mask = 0.0; s_m1 = 0.0; s_m2 = 0.0; }
    if (tid < 64) { s_klb[tid] = 0.0; s_mb[tid] = 0.0; }
    __syncthreads();

    double l = 0.0, mk = 0.0, a1 = 0.0, a2 = 0.0;
    for (int r = tid; r < M; r += blockDim.x) {
        int b = r / T;
        float m  = attn[r];
        float kl = g_kl[r];
        float lp = g_chosen_lp[r];
        float c1 = expf(lp - lp);
        float c2 = fminf(fmaxf(c1, 1.0f - 0.2f), 1.0f + 0.2f);
        float a  = adv[b];
        float ptl = -fminf(c1 * a, c2 * a) + 0.1f * kl;

        l  += (double)(ptl * m);
        mk += (double)m;
        a1 += (double)lp;
        a2 += (double)g_sumlogits[r] / (double)V - (double)g_lse[r];
        atomicAdd(&s_klb[b], (double)(kl * m));
        atomicAdd(&s_mb[b],  (double)m);
    }
    atomicAdd(&s_loss, l);
    atomicAdd(&s_mask, mk);
    atomicAdd(&s_m1,   a1);
    atomicAdd(&s_m2,   a2);
    __syncthreads();

    if (tid == 0) {
        double m3 = 0.0;
        for (int b = 0; b < Bn; b++) m3 += s_klb[b] / fmax(s_mb[b], 1.0);
        m3 /= (double)Bn;
        out[0] = (float)(s_loss / fmax(s_mask, 1.0));
        out[1] = (float)(s_m1 / (double)M);
        out[2] = (float)(s_m2 / (double)M);
        out[3] = (float)m3;
    }
}

// ---------------------------------------------------------------------------
extern "C" void kernel_launch(void* const* d_in, const int* in_sizes, int n_in,
                              void* d_out, int out_size)
{
    const float* x    = (const float*)d_in[0];
    const float* attn = (const float*)d_in[1];
    const float* adv  = (const float*)d_in[2];
    const float* ref  = (const float*)d_in[3];
    const float* Wm   = (const float*)d_in[4];
    const float* refW = (const float*)d_in[5];

    const int BT = in_sizes[1];          // B*T
    const int Bn = in_sizes[2];          // B
    const int T  = BT / Bn;
    const int H  = in_sizes[0] / BT;     // hidden
    const int V  = in_sizes[4] / H;      // vocab
    const int M  = BT;

    if (M % BM || V % BN || H % BK) return;            // unsupported shape
    const int nctw = (V / BN) * 4;                      // 32-col chunks
    if (M > MAX_M || nctw > MAX_CTW) return;

    cudaFuncSetAttribute(gemm_stats_tc<0>,
                         cudaFuncAttributeMaxDynamicSharedMemorySize, SMEM_BYTES);
    cudaFuncSetAttribute(gemm_stats_tc<1>,
                         cudaFuncAttributeMaxDynamicSharedMemorySize, SMEM_BYTES);

    dim3 grid(M / BM, V / BN);           // x fast-varying -> W tile L2 reuse

    gemm_stats_tc<0><<<grid, NTHREADS, SMEM_BYTES>>>(x, Wm, M, V, H, nctw);
    reduce_rows_x<<<(M * 32 + 255) / 256, 256>>>(M, nctw);
    gemm_stats_tc<1><<<grid, NTHREADS, SMEM_BYTES>>>(ref, refW, M, V, H, nctw);
    reduce_rows_ref<<<(M * 32 + 255) / 256, 256>>>(M, nctw);
    finalize_kernel<<<1, 1024>>>(attn, adv, Bn, T, M, V, (float*)d_out);
}